// round 10
// baseline (speedup 1.0000x reference)
#include <cuda_runtime.h>
#include <math.h>

#define NN        21
#define NN2       441
#define NFEAT     128
#define PAD       24
#define FC1_OUT   512
#define FC2_OUT   512
#define FC3_OUT   256
#define FC1_K     441
#define FC2_K     512
#define FC3_K     512

// ===========================================================================
//   PRIMARY: 16-CTA cluster, redundant quad-tiled GCN, 2 DSMEM handoffs
// ===========================================================================
#define CLN       16
#define CNT       512

__device__ __forceinline__ unsigned smem_u32(const void* p) {
    unsigned a;
    asm("{ .reg .u64 t; cvta.to.shared.u64 t, %1; cvt.u32.u64 %0, t; }"
        : "=r"(a) : "l"(p));
    return a;
}
__device__ __forceinline__ unsigned mapa_rank(unsigned laddr, unsigned r) {
    unsigned ra;
    asm("mapa.shared::cluster.u32 %0, %1, %2;" : "=r"(ra) : "r"(laddr), "r"(r));
    return ra;
}
__device__ __forceinline__ void st_cluster_f32(unsigned addr, float v) {
    asm volatile("st.shared::cluster.f32 [%0], %1;" :: "r"(addr), "f"(v) : "memory");
}
__device__ __forceinline__ void mbar_init(unsigned a, unsigned cnt) {
    asm volatile("mbarrier.init.shared.b64 [%0], %1;" :: "r"(a), "r"(cnt) : "memory");
}
__device__ __forceinline__ void mbar_arrive_remote(unsigned laddr, unsigned r) {
    unsigned ra = mapa_rank(laddr, r);
    asm volatile("mbarrier.arrive.release.cluster.shared::cluster.b64 _, [%0];"
                 :: "r"(ra) : "memory");
}
__device__ __forceinline__ void mbar_wait0(unsigned a) {
    asm volatile(
        "{ .reg .pred P;\n"
        "WL_%=: mbarrier.try_wait.parity.acquire.cluster.shared::cta.b64 P, [%0], 0, 0x989680;\n"
        " @P bra WD_%=;\n"
        " bra WL_%=;\n"
        "WD_%=: }\n" :: "r"(a) : "memory");
}
__device__ __forceinline__ void fence_cluster() {
    asm volatile("fence.acq_rel.cluster;" ::: "memory");
}
#define BAR(id, n) asm volatile("bar.sync %0, %1;" :: "r"(id), "r"(n) : "memory")

__global__ void __launch_bounds__(CNT, 1)
cluster_net_kernel(const float* __restrict__ state,
                   const int*   __restrict__ edge_index, int n_edges,
                   const float* __restrict__ W1,  const float* __restrict__ b1,
                   const float* __restrict__ W2,  const float* __restrict__ b2,
                   const float* __restrict__ Wf1, const float* __restrict__ bf1,
                   const float* __restrict__ Wf2, const float* __restrict__ bf2,
                   const float* __restrict__ Wf3, const float* __restrict__ bf3,
                   float* __restrict__ out)
{
    __shared__ float sx1[512];
    __shared__ float sx2[512];
    __shared__ float red[512];
    __shared__ float sv[448];               // final v, unpadded 441 (+pad0)
    __shared__ float sA[448];               // A_norm, unpadded
    __shared__ float sX[NN * NFEAT];        // 2688
    __shared__ float sW1q[NFEAT * PAD];     // 3072, zero-padded cols 21..23
    __shared__ float sW2q[NN * PAD];        // 504,  zero-padded
    __shared__ float sBq[NN * PAD];         // stage buffer (padded)
    __shared__ float sCq[NN * PAD];         // stage buffer (padded)
    __shared__ float4 sPartq[128];          // h1 k-split partials
    __shared__ float sb1q[PAD], sb2q[PAD], sdinv[32];
    __shared__ unsigned long long mbX1, mbX2;

    const int t  = threadIdx.x;
    const int b  = blockIdx.x;              // cluster rank
    const int j  = t & 31;
    const int kg = t >> 5;

    const unsigned sx1_a  = smem_u32(sx1);
    const unsigned sx2_a  = smem_u32(sx2);
    const unsigned mbX1_a = smem_u32(&mbX1);
    const unsigned mbX2_a = smem_u32(&mbX2);

    // ---- edge prefetch (adjacency group threads: 256..383) ----
    int er = -1, ec = -1;
    if (t >= 256 && t < 384) {
        int u = t - 256;
        if (u < n_edges) {
            er = __ldcg(&edge_index[u]);
            ec = __ldcg(&edge_index[n_edges + u]);
        }
    }

    // ---- FC weight/bias register preloads (issued early, overlap GCN) ----
    const int k1 = kg * 28;
    float w1r[28];
    #pragma unroll
    for (int kk = 0; kk < 28; kk++) {
        int k = k1 + kk;
        w1r[kk] = (k < FC1_K) ? __ldg(&Wf1[k * FC1_OUT + b * 32 + j]) : 0.f;
    }
    const int k2 = kg * 32;
    float w2r[32];
    #pragma unroll
    for (int kk = 0; kk < 32; kk++)
        w2r[kk] = __ldg(&Wf2[(k2 + kk) * FC2_OUT + b * 32 + j]);
    const int o3 = j & 15;
    const int kh3 = j >> 4;
    const int k3 = kg * 32 + kh3 * 16;
    float w3r[16];
    #pragma unroll
    for (int kk = 0; kk < 16; kk++)
        w3r[kk] = __ldg(&Wf3[(k3 + kk) * FC3_OUT + b * 16 + o3]);
    const float bias1 = (t < 32) ? __ldg(&bf1[b * 32 + t]) : 0.f;
    const float bias2 = (t < 32) ? __ldg(&bf2[b * 32 + t]) : 0.f;
    const float bias3 = (t < 16) ? __ldg(&bf3[b * 16 + t]) : 0.f;

    // ---- staging: sX, padded sW1q/sW2q/biases, zero sA/sv tail ----
    {
        const float4* X4 = (const float4*)state;
        float4* dX = (float4*)sX;
        for (int i = t; i < 672; i += CNT) dX[i] = X4[i];
        for (int i = t; i < NFEAT * PAD; i += CNT) {
            int f = i / PAD, jj = i % PAD;
            sW1q[i] = (jj < NN) ? __ldg(&W1[f * NN + jj]) : 0.f;
        }
        for (int i = t; i < NN * PAD; i += CNT) {
            int k = i / PAD, jj = i % PAD;
            sW2q[i] = (jj < NN) ? __ldg(&W2[k * NN + jj]) : 0.f;
        }
        if (t < NN2) sA[t] = 0.f;
        if (t >= 441 && t < 448) { sA[t] = 0.f; sv[t] = 0.f; }
        if (t < PAD)  sb1q[t] = (t < NN) ? __ldg(&b1[t]) : 0.f;
        if (t >= 32 && t < 32 + PAD) {
            int u = t - 32;
            sb2q[u] = (u < NN) ? __ldg(&b2[u]) : 0.f;
        }
    }
    if (t == 0) { mbar_init(mbX1_a, CLN); mbar_init(mbX2_a, CLN); }
    __syncthreads();
    asm volatile("barrier.cluster.arrive.aligned;" ::: "memory");   // wait later

    // ================= h1 (warps 0-7)  ||  adjacency (warps 8-11) =========
    if (t < 256) {
        // h1 = X @ W1 : 1x4 tiles, 2-way k-split
        const int kh = t >> 7;              // 0/1
        const int s  = t & 127;
        float4 acc0 = {0.f, 0.f, 0.f, 0.f};
        float4 acc1 = {0.f, 0.f, 0.f, 0.f};
        if (s < 126) {
            const int i  = s / 6, jq = s % 6;
            const float*  xr = &sX[i * NFEAT + kh * 64];
            const float4* wq = (const float4*)&sW1q[(kh * 64) * PAD] + jq;
            #pragma unroll 16
            for (int f = 0; f < 64; f += 2) {
                float x0 = xr[f],     x1 = xr[f + 1];
                float4 w0 = wq[f * 6], w1 = wq[(f + 1) * 6];
                acc0.x += x0 * w0.x; acc0.y += x0 * w0.y;
                acc0.z += x0 * w0.z; acc0.w += x0 * w0.w;
                acc1.x += x1 * w1.x; acc1.y += x1 * w1.y;
                acc1.z += x1 * w1.z; acc1.w += x1 * w1.w;
            }
        }
        if (kh == 1 && s < 126) {
            float4 p = {acc0.x + acc1.x, acc0.y + acc1.y,
                        acc0.z + acc1.z, acc0.w + acc1.w};
            sPartq[s] = p;
        }
        BAR(1, 256);
        if (kh == 0 && s < 126) {
            float4 p = sPartq[s];
            float4 r = {acc0.x + acc1.x + p.x, acc0.y + acc1.y + p.y,
                        acc0.z + acc1.z + p.z, acc0.w + acc1.w + p.w};
            ((float4*)sBq)[s] = r;          // sBq[i*24 + 4*jq]
        }
    } else if (t < 384) {
        // adjacency chain on warps 8-11 (128 threads), named barrier 2
        const int u = t - 256;
        BAR(2, 128);                        // sA zeroed in staging (pre-sync)
        if (er >= 0) atomicAdd(&sA[er * NN + ec], 1.0f);
        BAR(2, 128);
        if (u < NN) sA[u * NN + u] += 1.0f;
        BAR(2, 128);
        if (u < NN) {
            float d = 0.f;
            #pragma unroll
            for (int i = 0; i < NN; i++) d += sA[i * NN + u];
            sdinv[u] = (d > 0.f) ? rsqrtf(d) : 0.f;
        }
        BAR(2, 128);
        for (int i = u; i < NN2; i += 128) {
            int ii = i / NN, jj = i % NN;
            sA[i] *= sdinv[ii] * sdinv[jj];
        }
    }
    __syncthreads();                        // join: sBq + sA ready

    // ======== g1 / h2 / v : quad tiles on warps 0-3 =======================
    if (t < 128) {
        const int i  = t / 6, jq = t % 6;   // valid for t<126
        if (t < 126) {                      // g1 = A @ h1 + b1
            const float*  ar = &sA[i * NN];
            const float4* bq = (const float4*)sBq + jq;
            float4 a = ((const float4*)sb1q)[jq];
            #pragma unroll
            for (int k = 0; k < NN; k++) {
                float av = ar[k];
                float4 h = bq[k * 6];
                a.x += av * h.x; a.y += av * h.y;
                a.z += av * h.z; a.w += av * h.w;
            }
            ((float4*)sCq)[t] = a;
        }
        BAR(1, 128);
        if (t < 126) {                      // h2 = g1 @ W2
            const float*  gr = &sCq[i * PAD];
            const float4* wq = (const float4*)sW2q + jq;
            float4 a = {0.f, 0.f, 0.f, 0.f};
            #pragma unroll
            for (int k = 0; k < NN; k++) {
                float gv = gr[k];
                float4 w = wq[k * 6];
                a.x += gv * w.x; a.y += gv * w.y;
                a.z += gv * w.z; a.w += gv * w.w;
            }
            ((float4*)sBq)[t] = a;
        }
        BAR(1, 128);
        if (t < 126) {                      // v = A @ h2 + b2 (unpadded store)
            const float*  ar = &sA[i * NN];
            const float4* bq = (const float4*)sBq + jq;
            float4 a = ((const float4*)sb2q)[jq];
            #pragma unroll
            for (int k = 0; k < NN; k++) {
                float av = ar[k];
                float4 h = bq[k * 6];
                a.x += av * h.x; a.y += av * h.y;
                a.z += av * h.z; a.w += av * h.w;
            }
            int base = i * NN + jq * 4;
            int lim  = NN - jq * 4;         // 21-20=1 for jq=5
            sv[base] = a.x;
            if (lim > 1) sv[base + 1] = a.y;
            if (lim > 2) sv[base + 2] = a.z;
            if (lim > 3) sv[base + 3] = a.w;
        }
    }
    __syncthreads();                        // sv ready for all 16 warps

    // ======================= FC1 (local v, 32 outs) =======================
    {
        float a0 = 0.f, a1 = 0.f, a2 = 0.f, a3 = 0.f;
        #pragma unroll
        for (int kk = 0; kk < 28; kk += 4) {
            a0 += sv[k1 + kk]     * w1r[kk];
            a1 += sv[k1 + kk + 1] * w1r[kk + 1];
            a2 += sv[k1 + kk + 2] * w1r[kk + 2];
            a3 += sv[k1 + kk + 3] * w1r[kk + 3];
        }
        red[t] = (a0 + a1) + (a2 + a3);
    }
    asm volatile("barrier.cluster.wait.aligned;" ::: "memory");  // before push
    __syncthreads();
    if (t < 32) {
        float s0 = red[t]       + red[t + 32];
        float s1 = red[t + 64]  + red[t + 96];
        float s2 = red[t + 128] + red[t + 160];
        float s3 = red[t + 192] + red[t + 224];
        float s4 = red[t + 256] + red[t + 288];
        float s5 = red[t + 320] + red[t + 352];
        float s6 = red[t + 384] + red[t + 416];
        float s7 = red[t + 448] + red[t + 480];
        float x  = fmaxf(((s0 + s1) + (s2 + s3)) + ((s4 + s5) + (s6 + s7)) + bias1, 0.f);
        unsigned laddr = sx1_a + (b * 32 + t) * 4;
        #pragma unroll
        for (int r = 0; r < CLN; r++) st_cluster_f32(mapa_rank(laddr, r), x);
        __syncwarp();
        fence_cluster();
        if (t < CLN) mbar_arrive_remote(mbX1_a, (unsigned)t);
    }

    // ======================= FC2 ==========================================
    if (t == 0) mbar_wait0(mbX1_a);
    __syncthreads();
    {
        float a0 = 0.f, a1 = 0.f, a2 = 0.f, a3 = 0.f;
        #pragma unroll
        for (int kk = 0; kk < 32; kk += 4) {
            a0 += sx1[k2 + kk]     * w2r[kk];
            a1 += sx1[k2 + kk + 1] * w2r[kk + 1];
            a2 += sx1[k2 + kk + 2] * w2r[kk + 2];
            a3 += sx1[k2 + kk + 3] * w2r[kk + 3];
        }
        red[t] = (a0 + a1) + (a2 + a3);
    }
    __syncthreads();
    if (t < 32) {
        float s0 = red[t]       + red[t + 32];
        float s1 = red[t + 64]  + red[t + 96];
        float s2 = red[t + 128] + red[t + 160];
        float s3 = red[t + 192] + red[t + 224];
        float s4 = red[t + 256] + red[t + 288];
        float s5 = red[t + 320] + red[t + 352];
        float s6 = red[t + 384] + red[t + 416];
        float s7 = red[t + 448] + red[t + 480];
        float x  = fmaxf(((s0 + s1) + (s2 + s3)) + ((s4 + s5) + (s6 + s7)) + bias2, 0.f);
        unsigned laddr = sx2_a + (b * 32 + t) * 4;
        #pragma unroll
        for (int r = 0; r < CLN; r++) st_cluster_f32(mapa_rank(laddr, r), x);
        __syncwarp();
        fence_cluster();
        if (t < CLN) mbar_arrive_remote(mbX2_a, (unsigned)t);
    }

    // ======================= FC3 (16 outs per block) ======================
    if (t == 0) mbar_wait0(mbX2_a);
    __syncthreads();
    {
        float a0 = 0.f, a1 = 0.f, a2 = 0.f, a3 = 0.f;
        #pragma unroll
        for (int kk = 0; kk < 16; kk += 4) {
            a0 += sx2[k3 + kk]     * w3r[kk];
            a1 += sx2[k3 + kk + 1] * w3r[kk + 1];
            a2 += sx2[k3 + kk + 2] * w3r[kk + 2];
            a3 += sx2[k3 + kk + 3] * w3r[kk + 3];
        }
        red[t] = (a0 + a1) + (a2 + a3);
    }
    __syncthreads();
    if (t < 16) {
        float s = 0.f;
        #pragma unroll
        for (int g = 0; g < 16; g++)
            s += red[g * 32 + t] + red[g * 32 + 16 + t];
        out[b * 16 + t] = fmaxf(s + bias3, 0.f);
    }
}

// ===========================================================================
//        FALLBACK: R6 global-flag kernel (proven)
// ===========================================================================
#define NBLK      41
#define NTHREADS  512

__device__ float g_p[448];
__device__ float g_v[448];
__device__ float g_x1[512];
__device__ float g_x2[512];
__device__ unsigned g_fp[7 * 32];
__device__ unsigned g_fv[32];
__device__ unsigned g_fx1[16 * 32];
__device__ unsigned g_fx2[16 * 32];

__device__ __forceinline__ unsigned ld_acq(unsigned* p) {
    unsigned v;
    asm volatile("ld.acquire.gpu.global.u32 %0, [%1];" : "=r"(v) : "l"(p) : "memory");
    return v;
}
__device__ __forceinline__ unsigned ld_plain(unsigned* p) {
    unsigned v;
    asm volatile("ld.global.cg.u32 %0, [%1];" : "=r"(v) : "l"(p) : "memory");
    return v;
}
__device__ __forceinline__ void publish(unsigned* p) {
    asm volatile("red.release.gpu.global.add.u32 [%0], 1;" :: "l"(p) : "memory");
}
__device__ __forceinline__ void wait_flag(unsigned* p, unsigned old) {
    while (ld_acq(p) == old) { }
}

__global__ void __launch_bounds__(NTHREADS, 1)
fused_net_kernel(const float* __restrict__ state,
                 const int*   __restrict__ edge_index, int n_edges,
                 const float* __restrict__ W1,  const float* __restrict__ b1,
                 const float* __restrict__ W2,  const float* __restrict__ b2,
                 const float* __restrict__ Wf1, const float* __restrict__ bf1,
                 const float* __restrict__ Wf2, const float* __restrict__ bf2,
                 const float* __restrict__ Wf3, const float* __restrict__ bf3,
                 float* __restrict__ out)
{
    __shared__ float sh[4608];
    const int t = threadIdx.x;
    const int b = blockIdx.x;
    const int j  = t & 31;
    const int kg = t >> 5;

    if (b == 0) {
        float* sA    = sh;
        float* sA2   = sh + 448;
        float* sP    = sh + 896;
        float* sW2   = sh + 1344;
        float* sb1   = sh + 1792;
        float* sb2   = sh + 1824;
        float* sr    = sh + 1856;
        float* sc    = sh + 1888;
        float* sdinv = sh + 1920;
        unsigned* soldp = (unsigned*)(sh + 1952);

        if (t < 7) soldp[t] = ld_plain(&g_fp[t * 32]);
        if (t < NN2) { sA[t] = 0.f; sW2[t] = W2[t]; }
        if (t < NN)  { sb1[t] = b1[t]; sb2[t] = b2[t]; }
        __syncthreads();
        for (int e = t; e < n_edges; e += NTHREADS) {
            int r = edge_index[e];
            int c = edge_index[n_edges + e];
            atomicAdd(&sA[r * NN + c], 1.0f);
        }
        __syncthreads();
        if (t < NN) sA[t * NN + t] += 1.0f;
        __syncthreads();
        if (t < NN) {
            float d = 0.f;
            #pragma unroll
            for (int i = 0; i < NN; i++) d += sA[i * NN + t];
            sdinv[t] = (d > 0.f) ? rsqrtf(d) : 0.f;
        }
        __syncthreads();
        if (t < NN2) {
            int i = t / NN, jj = t % NN;
            sA[t] *= sdinv[i] * sdinv[jj];
        }
        __syncthreads();
        if (t < NN2) {
            int i = t / NN, jj = t % NN;
            float a0 = 0.f, a1 = 0.f;
            #pragma unroll
            for (int k = 0; k < 20; k += 2) {
                a0 += sA[i * NN + k]     * sA[k * NN + jj];
                a1 += sA[i * NN + k + 1] * sA[(k + 1) * NN + jj];
            }
            a0 += sA[i * NN + 20] * sA[20 * NN + jj];
            sA2[t] = a0 + a1;
        }
        if (t >= 448 && t < 448 + NN) {
            int i = t - 448;
            float s = 0.f;
            #pragma unroll
            for (int k = 0; k < NN; k++) s += sA[i * NN + k];
            sr[i] = s;
        }
        if (t >= 480 && t < 480 + NN) {
            int jj = t - 480;
            float s = 0.f;
            #pragma unroll
            for (int k = 0; k < NN; k++) s += sb1[k] * sW2[k * NN + jj];
            sc[jj] = s;
        }
        __syncthreads();
        if (kg < 7 && j == 0) wait_flag(&g_fp[kg * 32], soldp[kg]);
        __syncthreads();
        if (t < NN2) sP[t] = __ldcg(&g_p[t]);
        __syncthreads();
        if (t < NN2) {
            int i = t / NN, jj = t % NN;
            float a0 = sr[i] * sc[jj] + sb2[jj];
            float a1 = 0.f;
            #pragma unroll
            for (int k = 0; k < 20; k += 2) {
                a0 += sA2[i * NN + k]     * sP[k * NN + jj];
                a1 += sA2[i * NN + k + 1] * sP[(k + 1) * NN + jj];
            }
            a0 += sA2[i * NN + 20] * sP[20 * NN + jj];
            g_v[t] = a0 + a1;
        }
        __syncthreads();
        if (t == 0) { __threadfence(); publish(&g_fv[0]); }
        return;
    }

    float* red = sh;

    if (b <= 16) {
        const int jt = b - 1;
        const unsigned oldv = ld_plain(&g_fv[0]);
        const float bias = (t < 32) ? __ldg(&bf1[jt * 32 + t]) : 0.f;
        const int k0 = kg * 28;
        float w[28];
        #pragma unroll
        for (int kk = 0; kk < 28; kk++) {
            int k = k0 + kk;
            w[kk] = (k < FC1_K) ? __ldg(&Wf1[k * FC1_OUT + jt * 32 + j]) : 0.f;
        }
        wait_flag(&g_fv[0], oldv);
        float xv = (j < 28) ? __ldcg(&g_v[k0 + j]) : 0.f;
        float a0 = 0.f, a1 = 0.f, a2 = 0.f, a3 = 0.f;
        #pragma unroll
        for (int kk = 0; kk < 28; kk += 4) {
            a0 += __shfl_sync(0xffffffffu, xv, kk)     * w[kk];
            a1 += __shfl_sync(0xffffffffu, xv, kk + 1) * w[kk + 1];
            a2 += __shfl_sync(0xffffffffu, xv, kk + 2) * w[kk + 2];
            a3 += __shfl_sync(0xffffffffu, xv, kk + 3) * w[kk + 3];
        }
        red[t] = (a0 + a1) + (a2 + a3);
        __syncthreads();
        if (t < 32) {
            float s0 = red[t]       + red[t + 32];
            float s1 = red[t + 64]  + red[t + 96];
            float s2 = red[t + 128] + red[t + 160];
            float s3 = red[t + 192] + red[t + 224];
            float s4 = red[t + 256] + red[t + 288];
            float s5 = red[t + 320] + red[t + 352];
            float s6 = red[t + 384] + red[t + 416];
            float s7 = red[t + 448] + red[t + 480];
            float s  = ((s0 + s1) + (s2 + s3)) + ((s4 + s5) + (s6 + s7));
            g_x1[jt * 32 + t] = fmaxf(s + bias, 0.f);
            __syncwarp();
            if (t == 0) { __threadfence(); publish(&g_fx1[jt * 32]); }
        }
        return;
    }

    if (b <= 32) {
        const int jt = b - 17;
        unsigned oldf = 0;
        if (j == 0) oldf = ld_plain(&g_fx1[kg * 32]);
        oldf = __shfl_sync(0xffffffffu, oldf, 0);
        const float bias = (t < 32) ? __ldg(&bf2[jt * 32 + t]) : 0.f;
        const int k0 = kg * 32;
        float w[32];
        #pragma unroll
        for (int kk = 0; kk < 32; kk++)
            w[kk] = __ldg(&Wf2[(k0 + kk) * FC2_OUT + jt * 32 + j]);
        if (j == 0) wait_flag(&g_fx1[kg * 32], oldf);
        __syncwarp();
        float xv = __ldcg(&g_x1[k0 + j]);
        float a0 = 0.f, a1 = 0.f, a2 = 0.f, a3 = 0.f;
        #pragma unroll
        for (int kk = 0; kk < 32; kk += 4) {
            a0 += __shfl_sync(0xffffffffu, xv, kk)     * w[kk];
            a1 += __shfl_sync(0xffffffffu, xv, kk + 1) * w[kk + 1];
            a2 += __shfl_sync(0xffffffffu, xv, kk + 2) * w[kk + 2];
            a3 += __shfl_sync(0xffffffffu, xv, kk + 3) * w[kk + 3];
        }
        red[t] = (a0 + a1) + (a2 + a3);
        __syncthreads();
        if (t < 32) {
            float s0 = red[t]       + red[t + 32];
            float s1 = red[t + 64]  + red[t + 96];
            float s2 = red[t + 128] + red[t + 160];
            float s3 = red[t + 192] + red[t + 224];
            float s4 = red[t + 256] + red[t + 288];
            float s5 = red[t + 320] + red[t + 352];
            float s6 = red[t + 384] + red[t + 416];
            float s7 = red[t + 448] + red[t + 480];
            float s  = ((s0 + s1) + (s2 + s3)) + ((s4 + s5) + (s6 + s7));
            g_x2[jt * 32 + t] = fmaxf(s + bias, 0.f);
            __syncwarp();
            if (t == 0) { __threadfence(); publish(&g_fx2[jt * 32]); }
        }
        return;
    }

    {
        const int g3 = b - 33;
        unsigned oldf = 0;
        if (j == 0) oldf = ld_plain(&g_fx2[kg * 32]);
        oldf = __shfl_sync(0xffffffffu, oldf, 0);

        if (g3 < 7) {
            float* sXr  = sh;
            float* sW1g = sh + 384;
            float* sW2s = sh + 3072;
            float* sH   = sh + 3520;
            float* pr   = sh + 3584;
            const int R0 = g3 * 3;
            {
                const float4* X4 = (const float4*)(state + R0 * NFEAT);
                float4* d4 = (float4*)sXr;
                if (t < 96) d4[t] = X4[t];
                const float4* W14 = (const float4*)W1;
                float4* w14 = (float4*)sW1g;
                for (int i = t; i < 672; i += NTHREADS) w14[i] = W14[i];
                if (t < NN2) sW2s[t] = W2[t];
            }
            __syncthreads();
            if (t < 504) {
                int o  = t >> 3;
                int s  = t & 7;
                int ri = o / NN, jj = o % NN;
                int kk0 = s * 16;
                float a0 = 0.f, a1 = 0.f, a2 = 0.f, a3 = 0.f;
                #pragma unroll
                for (int kk = 0; kk < 16; kk += 4) {
                    a0 += sXr[ri * NFEAT + kk0 + kk]     * sW1g[(kk0 + kk)     * NN + jj];
                    a1 += sXr[ri * NFEAT + kk0 + kk + 1] * sW1g[(kk0 + kk + 1) * NN + jj];
                    a2 += sXr[ri * NFEAT + kk0 + kk + 2] * sW1g[(kk0 + kk + 2) * NN + jj];
                    a3 += sXr[ri * NFEAT + kk0 + kk + 3] * sW1g[(kk0 + kk + 3) * NN + jj];
                }
                pr[t] = (a0 + a1) + (a2 + a3);
            }
            __syncthreads();
            if (t < 63) {
                float s0 = pr[t * 8]     + pr[t * 8 + 1];
                float s1 = pr[t * 8 + 2] + pr[t * 8 + 3];
                float s2 = pr[t * 8 + 4] + pr[t * 8 + 5];
                float s3 = pr[t * 8 + 6] + pr[t * 8 + 7];
                sH[t] = (s0 + s1) + (s2 + s3);
            }
            __syncthreads();
            if (t < 63) {
                int ri = t / NN, jj = t % NN;
                float a0 = 0.f, a1 = 0.f;
                #pragma unroll
                for (int k = 0; k < 20; k += 2) {
                    a0 += sH[ri * NN + k]     * sW2s[k * NN + jj];
                    a1 += sH[ri * NN + k + 1] * sW2s[(k + 1) * NN + jj];
                }
                a0 += sH[ri * NN + 20] * sW2s[20 * NN + jj];
                g_p[(R0 + ri) * NN + jj] = a0 + a1;
            }
            __syncthreads();
            if (t == 0) { __threadfence(); publish(&g_fp[g3 * 32]); }
            __syncthreads();
        }

        const float bias = (t < 32) ? __ldg(&bf3[g3 * 32 + t]) : 0.f;
        const int k0 = kg * 32;
        float w[32];
        #pragma unroll
        for (int kk = 0; kk < 32; kk++)
            w[kk] = __ldg(&Wf3[(k0 + kk) * FC3_OUT + g3 * 32 + j]);
        if (j == 0) wait_flag(&g_fx2[kg * 32], oldf);
        __syncwarp();
        float xv = __ldcg(&g_x2[k0 + j]);
        float a0 = 0.f, a1 = 0.f, a2 = 0.f, a3 = 0.f;
        #pragma unroll
        for (int kk = 0; kk < 32; kk += 4) {
            a0 += __shfl_sync(0xffffffffu, xv, kk)     * w[kk];
            a1 += __shfl_sync(0xffffffffu, xv, kk + 1) * w[kk + 1];
            a2 += __shfl_sync(0xffffffffu, xv, kk + 2) * w[kk + 2];
            a3 += __shfl_sync(0xffffffffu, xv, kk + 3) * w[kk + 3];
        }
        red[t] = (a0 + a1) + (a2 + a3);
        __syncthreads();
        if (t < 32) {
            float s0 = red[t]       + red[t + 32];
            float s1 = red[t + 64]  + red[t + 96];
            float s2 = red[t + 128] + red[t + 160];
            float s3 = red[t + 192] + red[t + 224];
            float s4 = red[t + 256] + red[t + 288];
            float s5 = red[t + 320] + red[t + 352];
            float s6 = red[t + 384] + red[t + 416];
            float s7 = red[t + 448] + red[t + 480];
            float s  = ((s0 + s1) + (s2 + s3)) + ((s4 + s5) + (s6 + s7));
            out[g3 * 32 + t] = fmaxf(s + bias, 0.f);
        }
    }
}

// ---------------------------------------------------------------------------
extern "C" void kernel_launch(void* const* d_in, const int* in_sizes, int n_in,
                              void* d_out, int out_size)
{
    const float* state = (const float*)d_in[0];
    const int*   edges = (const int*)  d_in[1];
    const int n_edges  = in_sizes[1] / 2;

    const float* W1  = (const float*)d_in[2];
    const float* b1  = (const float*)d_in[3];
    const float* W2  = (const float*)d_in[4];
    const float* b2  = (const float*)d_in[5];
    const float* Wf1 = (const float*)d_in[6];
    const float* bf1 = (const float*)d_in[7];
    const float* Wf2 = (const float*)d_in[8];
    const float* bf2 = (const float*)d_in[9];
    const float* Wf3 = (const float*)d_in[10];
    const float* bf3 = (const float*)d_in[11];
    float* out = (float*)d_out;

    static int use16 = -1;
    if (use16 < 0) {
        cudaFuncSetAttribute(cluster_net_kernel,
                             cudaFuncAttributeNonPortableClusterSizeAllowed, 1);
        cudaLaunchConfig_t probe = {};
        probe.gridDim  = {CLN, 1, 1};
        probe.blockDim = {CNT, 1, 1};
        cudaLaunchAttribute pa[1];
        pa[0].id = cudaLaunchAttributeClusterDimension;
        pa[0].val.clusterDim = {CLN, 1, 1};
        probe.attrs = pa;
        probe.numAttrs = 1;
        int nclust = 0;
        cudaError_t e = cudaOccupancyMaxActiveClusters(&nclust, cluster_net_kernel, &probe);
        use16 = (e == cudaSuccess && nclust >= 1) ? 1 : 0;
        cudaGetLastError();
    }

    if (use16) {
        cudaLaunchConfig_t cfg = {};
        cfg.gridDim  = {CLN, 1, 1};
        cfg.blockDim = {CNT, 1, 1};
        cudaLaunchAttribute attrs[1];
        attrs[0].id = cudaLaunchAttributeClusterDimension;
        attrs[0].val.clusterDim = {CLN, 1, 1};
        cfg.attrs = attrs;
        cfg.numAttrs = 1;
        cudaLaunchKernelEx(&cfg, cluster_net_kernel,
                           state, edges, n_edges, W1, b1, W2, b2,
                           Wf1, bf1, Wf2, bf2, Wf3, bf3, out);
    } else {
        fused_net_kernel<<<NBLK, NTHREADS>>>(
            state, edges, n_edges, W1, b1, W2, b2,
            Wf1, bf1, Wf2, bf2, Wf3, bf3, out);
    }
}

// round 11
// speedup vs baseline: 1.1805x; 1.1805x over previous
#include <cuda_runtime.h>
#include <math.h>

#define NN        21
#define NN2       441
#define NFEAT     128
#define FC1_OUT   512
#define FC2_OUT   512
#define FC3_OUT   256
#define FC1_K     441
#define FC2_K     512
#define FC3_K     512

// ===========================================================================
//   PRIMARY: 16-CTA cluster, redundant GCN (adj ∥ h1), 2 DSMEM handoffs
// ===========================================================================
#define CLN       16
#define CNT       512

__device__ __forceinline__ unsigned smem_u32(const void* p) {
    unsigned a;
    asm("{ .reg .u64 t; cvta.to.shared.u64 t, %1; cvt.u32.u64 %0, t; }"
        : "=r"(a) : "l"(p));
    return a;
}
__device__ __forceinline__ unsigned mapa_rank(unsigned laddr, unsigned r) {
    unsigned ra;
    asm("mapa.shared::cluster.u32 %0, %1, %2;" : "=r"(ra) : "r"(laddr), "r"(r));
    return ra;
}
__device__ __forceinline__ void st_cluster_f32(unsigned addr, float v) {
    asm volatile("st.shared::cluster.f32 [%0], %1;" :: "r"(addr), "f"(v) : "memory");
}
__device__ __forceinline__ void mbar_init(unsigned a, unsigned cnt) {
    asm volatile("mbarrier.init.shared.b64 [%0], %1;" :: "r"(a), "r"(cnt) : "memory");
}
__device__ __forceinline__ void mbar_arrive_remote(unsigned laddr, unsigned r) {
    unsigned ra = mapa_rank(laddr, r);
    asm volatile("mbarrier.arrive.release.cluster.shared::cluster.b64 _, [%0];"
                 :: "r"(ra) : "memory");
}
__device__ __forceinline__ void mbar_wait0(unsigned a) {
    asm volatile(
        "{ .reg .pred P;\n"
        "WL_%=: mbarrier.try_wait.parity.acquire.cluster.shared::cta.b64 P, [%0], 0, 0x989680;\n"
        " @P bra WD_%=;\n"
        " bra WL_%=;\n"
        "WD_%=: }\n" :: "r"(a) : "memory");
}
__device__ __forceinline__ void fence_cluster() {
    asm volatile("fence.acq_rel.cluster;" ::: "memory");
}
#define BAR(id, n) asm volatile("bar.sync %0, %1;" :: "r"(id), "r"(n) : "memory")

__global__ void __launch_bounds__(CNT, 1)
cluster_net_kernel(const float* __restrict__ state,
                   const int*   __restrict__ edge_index, int n_edges,
                   const float* __restrict__ W1,  const float* __restrict__ b1,
                   const float* __restrict__ W2,  const float* __restrict__ b2,
                   const float* __restrict__ Wf1, const float* __restrict__ bf1,
                   const float* __restrict__ Wf2, const float* __restrict__ bf2,
                   const float* __restrict__ Wf3, const float* __restrict__ bf3,
                   float* __restrict__ out)
{
    __shared__ float sx1[512];
    __shared__ float sx2[512];
    __shared__ float red[512];
    __shared__ float sv[448];          // GCN output v (padded)
    __shared__ float sA[448];          // A_norm
    __shared__ float sB[448];          // stage buffer
    __shared__ float sC[448];          // stage buffer
    __shared__ float sX[NN * NFEAT];   // 2688
    __shared__ float sW1[NFEAT * NN];  // 2688
    __shared__ float sW2[448];
    __shared__ float sb1[32], sb2[32], sdinv[32];
    __shared__ unsigned long long mbX1, mbX2;

    const int t  = threadIdx.x;
    const int b  = blockIdx.x;         // cluster rank (grid = one cluster)
    const int j  = t & 31;
    const int kg = t >> 5;

    const unsigned sx1_a  = smem_u32(sx1);
    const unsigned sx2_a  = smem_u32(sx2);
    const unsigned mbX1_a = smem_u32(&mbX1);
    const unsigned mbX2_a = smem_u32(&mbX2);

    // ---- edge prefetch (adjacency group: threads 448..511, 2 edges each) --
    int er0 = -1, ec0 = -1, er1 = -1, ec1 = -1;
    if (t >= 448) {
        int u = t - 448;
        if (u < n_edges) {
            er0 = __ldcg(&edge_index[u]);
            ec0 = __ldcg(&edge_index[n_edges + u]);
        }
        if (u + 64 < n_edges) {
            er1 = __ldcg(&edge_index[u + 64]);
            ec1 = __ldcg(&edge_index[n_edges + u + 64]);
        }
    }

    // ---- FC1 weights only (28 regs live through GCN; FC2/FC3 deferred) ----
    const int k1 = kg * 28;
    float w1r[28];
    #pragma unroll
    for (int kk = 0; kk < 28; kk++) {
        int k = k1 + kk;
        w1r[kk] = (k < FC1_K) ? __ldg(&Wf1[k * FC1_OUT + b * 32 + j]) : 0.f;
    }
    const float bias1 = (t < 32) ? __ldg(&bf1[b * 32 + t]) : 0.f;

    // ---- GCN input staging (coalesced float4, L2-broadcast across ranks) --
    {
        const float4* X4  = (const float4*)state;
        const float4* W14 = (const float4*)W1;
        float4* dX = (float4*)sX;
        float4* dW = (float4*)sW1;
        for (int i = t; i < 672; i += CNT) { dX[i] = X4[i]; dW[i] = W14[i]; }
        if (t < NN2) { sA[t] = 0.f; sW2[t] = W2[t]; }
        if (t < NN)  { sb1[t] = b1[t]; sb2[t] = b2[t]; }
        if (t >= 441 && t < 448) { sv[t] = 0.f; }
    }
    if (t == 0) { mbar_init(mbX1_a, CLN); mbar_init(mbX2_a, CLN); }
    __syncthreads();
    asm volatile("barrier.cluster.arrive.aligned;" ::: "memory");  // wait later

    // ============ h1 (threads 0-447)  ||  adjacency (448-511) =============
    if (t < 448) {
        if (t < NN2) {
            int i = t / NN, jj = t % NN;
            const float4* xq = (const float4*)&sX[i * NFEAT];
            float a0 = 0.f, a1 = 0.f, a2 = 0.f, a3 = 0.f;
            #pragma unroll
            for (int f4 = 0; f4 < 32; f4++) {
                float4 x = xq[f4];
                int f = f4 * 4;
                a0 += x.x * sW1[f * NN + jj];
                a1 += x.y * sW1[(f + 1) * NN + jj];
                a2 += x.z * sW1[(f + 2) * NN + jj];
                a3 += x.w * sW1[(f + 3) * NN + jj];
            }
            sB[t] = (a0 + a1) + (a2 + a3);
        }
    } else {
        // adjacency chain on warps 14-15 (64 threads), named barrier 2
        const int u = t - 448;
        if (er0 >= 0) atomicAdd(&sA[er0 * NN + ec0], 1.0f);
        if (er1 >= 0) atomicAdd(&sA[er1 * NN + ec1], 1.0f);
        BAR(2, 64);
        if (u < NN) sA[u * NN + u] += 1.0f;
        BAR(2, 64);
        if (u < NN) {
            float d = 0.f;
            #pragma unroll
            for (int i = 0; i < NN; i++) d += sA[i * NN + u];
            sdinv[u] = (d > 0.f) ? rsqrtf(d) : 0.f;
        }
        BAR(2, 64);
        for (int i = u; i < NN2; i += 64) {
            int ii = i / NN, jj = i % NN;
            sA[i] *= sdinv[ii] * sdinv[jj];
        }
    }
    __syncthreads();                   // join: sB (h1) + sA (A_norm) ready

    // g1 = A @ h1 + b1
    if (t < NN2) {
        int i = t / NN, jj = t % NN;
        float a0 = sb1[jj], a1 = 0.f;
        #pragma unroll
        for (int k = 0; k < 20; k += 2) {
            a0 += sA[i * NN + k]     * sB[k * NN + jj];
            a1 += sA[i * NN + k + 1] * sB[(k + 1) * NN + jj];
        }
        a0 += sA[i * NN + 20] * sB[20 * NN + jj];
        sC[t] = a0 + a1;
    }
    __syncthreads();
    // h2 = g1 @ W2
    if (t < NN2) {
        int i = t / NN, jj = t % NN;
        float a0 = 0.f, a1 = 0.f;
        #pragma unroll
        for (int k = 0; k < 20; k += 2) {
            a0 += sC[i * NN + k]     * sW2[k * NN + jj];
            a1 += sC[i * NN + k + 1] * sW2[(k + 1) * NN + jj];
        }
        a0 += sC[i * NN + 20] * sW2[20 * NN + jj];
        sB[t] = a0 + a1;
    }
    __syncthreads();
    // v = A @ h2 + b2
    if (t < NN2) {
        int i = t / NN, jj = t % NN;
        float a0 = sb2[jj], a1 = 0.f;
        #pragma unroll
        for (int k = 0; k < 20; k += 2) {
            a0 += sA[i * NN + k]     * sB[k * NN + jj];
            a1 += sA[i * NN + k + 1] * sB[(k + 1) * NN + jj];
        }
        a0 += sA[i * NN + 20] * sB[20 * NN + jj];
        sv[t] = a0 + a1;
    }
    __syncthreads();

    // ======================= FC1 (local v, 32 outs) =======================
    {
        float a0 = 0.f, a1 = 0.f, a2 = 0.f, a3 = 0.f;
        #pragma unroll
        for (int kk = 0; kk < 28; kk += 4) {
            a0 += sv[k1 + kk]     * w1r[kk];
            a1 += sv[k1 + kk + 1] * w1r[kk + 1];
            a2 += sv[k1 + kk + 2] * w1r[kk + 2];
            a3 += sv[k1 + kk + 3] * w1r[kk + 3];
        }
        red[t] = (a0 + a1) + (a2 + a3);
    }
    asm volatile("barrier.cluster.wait.aligned;" ::: "memory");  // before push
    __syncthreads();
    if (t < 32) {
        float s0 = red[t]       + red[t + 32];
        float s1 = red[t + 64]  + red[t + 96];
        float s2 = red[t + 128] + red[t + 160];
        float s3 = red[t + 192] + red[t + 224];
        float s4 = red[t + 256] + red[t + 288];
        float s5 = red[t + 320] + red[t + 352];
        float s6 = red[t + 384] + red[t + 416];
        float s7 = red[t + 448] + red[t + 480];
        float x  = fmaxf(((s0 + s1) + (s2 + s3)) + ((s4 + s5) + (s6 + s7)) + bias1, 0.f);
        unsigned laddr = sx1_a + (b * 32 + t) * 4;
        #pragma unroll
        for (int r = 0; r < CLN; r++) st_cluster_f32(mapa_rank(laddr, r), x);
        __syncwarp();
        fence_cluster();
        if (t < CLN) mbar_arrive_remote(mbX1_a, (unsigned)t);
    }

    // ---- deferred FC2 weight loads (overlap the x1 handoff wait) ----
    const int k2 = kg * 32;
    float w2r[32];
    #pragma unroll
    for (int kk = 0; kk < 32; kk++)
        w2r[kk] = __ldg(&Wf2[(k2 + kk) * FC2_OUT + b * 32 + j]);
    const float bias2 = (t < 32) ? __ldg(&bf2[b * 32 + t]) : 0.f;

    // ======================= FC2 ==========================================
    if (t == 0) mbar_wait0(mbX1_a);
    __syncthreads();
    {
        float a0 = 0.f, a1 = 0.f, a2 = 0.f, a3 = 0.f;
        #pragma unroll
        for (int kk = 0; kk < 32; kk += 4) {
            a0 += sx1[k2 + kk]     * w2r[kk];
            a1 += sx1[k2 + kk + 1] * w2r[kk + 1];
            a2 += sx1[k2 + kk + 2] * w2r[kk + 2];
            a3 += sx1[k2 + kk + 3] * w2r[kk + 3];
        }
        red[t] = (a0 + a1) + (a2 + a3);
    }
    __syncthreads();
    if (t < 32) {
        float s0 = red[t]       + red[t + 32];
        float s1 = red[t + 64]  + red[t + 96];
        float s2 = red[t + 128] + red[t + 160];
        float s3 = red[t + 192] + red[t + 224];
        float s4 = red[t + 256] + red[t + 288];
        float s5 = red[t + 320] + red[t + 352];
        float s6 = red[t + 384] + red[t + 416];
        float s7 = red[t + 448] + red[t + 480];
        float x  = fmaxf(((s0 + s1) + (s2 + s3)) + ((s4 + s5) + (s6 + s7)) + bias2, 0.f);
        unsigned laddr = sx2_a + (b * 32 + t) * 4;
        #pragma unroll
        for (int r = 0; r < CLN; r++) st_cluster_f32(mapa_rank(laddr, r), x);
        __syncwarp();
        fence_cluster();
        if (t < CLN) mbar_arrive_remote(mbX2_a, (unsigned)t);
    }

    // ---- deferred FC3 weight loads (overlap the x2 handoff wait) ----
    const int o3 = j & 15;
    const int kh3 = j >> 4;
    const int k3 = kg * 32 + kh3 * 16;
    float w3r[16];
    #pragma unroll
    for (int kk = 0; kk < 16; kk++)
        w3r[kk] = __ldg(&Wf3[(k3 + kk) * FC3_OUT + b * 16 + o3]);
    const float bias3 = (t < 16) ? __ldg(&bf3[b * 16 + t]) : 0.f;

    // ======================= FC3 (16 outs per block) ======================
    if (t == 0) mbar_wait0(mbX2_a);
    __syncthreads();
    {
        float a0 = 0.f, a1 = 0.f, a2 = 0.f, a3 = 0.f;
        #pragma unroll
        for (int kk = 0; kk < 16; kk += 4) {
            a0 += sx2[k3 + kk]     * w3r[kk];
            a1 += sx2[k3 + kk + 1] * w3r[kk + 1];
            a2 += sx2[k3 + kk + 2] * w3r[kk + 2];
            a3 += sx2[k3 + kk + 3] * w3r[kk + 3];
        }
        red[t] = (a0 + a1) + (a2 + a3);
    }
    __syncthreads();
    if (t < 16) {
        float s = 0.f;
        #pragma unroll
        for (int g = 0; g < 16; g++)
            s += red[g * 32 + t] + red[g * 32 + 16 + t];
        out[b * 16 + t] = fmaxf(s + bias3, 0.f);
    }
}

// ===========================================================================
//        FALLBACK: R6 global-flag kernel (proven)
// ===========================================================================
#define NBLK      41
#define NTHREADS  512

__device__ float g_p[448];
__device__ float g_v[448];
__device__ float g_x1[512];
__device__ float g_x2[512];
__device__ unsigned g_fp[7 * 32];
__device__ unsigned g_fv[32];
__device__ unsigned g_fx1[16 * 32];
__device__ unsigned g_fx2[16 * 32];

__device__ __forceinline__ unsigned ld_acq(unsigned* p) {
    unsigned v;
    asm volatile("ld.acquire.gpu.global.u32 %0, [%1];" : "=r"(v) : "l"(p) : "memory");
    return v;
}
__device__ __forceinline__ unsigned ld_plain(unsigned* p) {
    unsigned v;
    asm volatile("ld.global.cg.u32 %0, [%1];" : "=r"(v) : "l"(p) : "memory");
    return v;
}
__device__ __forceinline__ void publish(unsigned* p) {
    asm volatile("red.release.gpu.global.add.u32 [%0], 1;" :: "l"(p) : "memory");
}
__device__ __forceinline__ void wait_flag(unsigned* p, unsigned old) {
    while (ld_acq(p) == old) { }
}

__global__ void __launch_bounds__(NTHREADS, 1)
fused_net_kernel(const float* __restrict__ state,
                 const int*   __restrict__ edge_index, int n_edges,
                 const float* __restrict__ W1,  const float* __restrict__ b1,
                 const float* __restrict__ W2,  const float* __restrict__ b2,
                 const float* __restrict__ Wf1, const float* __restrict__ bf1,
                 const float* __restrict__ Wf2, const float* __restrict__ bf2,
                 const float* __restrict__ Wf3, const float* __restrict__ bf3,
                 float* __restrict__ out)
{
    __shared__ float sh[4608];
    const int t = threadIdx.x;
    const int b = blockIdx.x;
    const int j  = t & 31;
    const int kg = t >> 5;

    if (b == 0) {
        float* sA    = sh;
        float* sA2   = sh + 448;
        float* sP    = sh + 896;
        float* sW2   = sh + 1344;
        float* sb1   = sh + 1792;
        float* sb2   = sh + 1824;
        float* sr    = sh + 1856;
        float* sc    = sh + 1888;
        float* sdinv = sh + 1920;
        unsigned* soldp = (unsigned*)(sh + 1952);

        if (t < 7) soldp[t] = ld_plain(&g_fp[t * 32]);
        if (t < NN2) { sA[t] = 0.f; sW2[t] = W2[t]; }
        if (t < NN)  { sb1[t] = b1[t]; sb2[t] = b2[t]; }
        __syncthreads();
        for (int e = t; e < n_edges; e += NTHREADS) {
            int r = edge_index[e];
            int c = edge_index[n_edges + e];
            atomicAdd(&sA[r * NN + c], 1.0f);
        }
        __syncthreads();
        if (t < NN) sA[t * NN + t] += 1.0f;
        __syncthreads();
        if (t < NN) {
            float d = 0.f;
            #pragma unroll
            for (int i = 0; i < NN; i++) d += sA[i * NN + t];
            sdinv[t] = (d > 0.f) ? rsqrtf(d) : 0.f;
        }
        __syncthreads();
        if (t < NN2) {
            int i = t / NN, jj = t % NN;
            sA[t] *= sdinv[i] * sdinv[jj];
        }
        __syncthreads();
        if (t < NN2) {
            int i = t / NN, jj = t % NN;
            float a0 = 0.f, a1 = 0.f;
            #pragma unroll
            for (int k = 0; k < 20; k += 2) {
                a0 += sA[i * NN + k]     * sA[k * NN + jj];
                a1 += sA[i * NN + k + 1] * sA[(k + 1) * NN + jj];
            }
            a0 += sA[i * NN + 20] * sA[20 * NN + jj];
            sA2[t] = a0 + a1;
        }
        if (t >= 448 && t < 448 + NN) {
            int i = t - 448;
            float s = 0.f;
            #pragma unroll
            for (int k = 0; k < NN; k++) s += sA[i * NN + k];
            sr[i] = s;
        }
        if (t >= 480 && t < 480 + NN) {
            int jj = t - 480;
            float s = 0.f;
            #pragma unroll
            for (int k = 0; k < NN; k++) s += sb1[k] * sW2[k * NN + jj];
            sc[jj] = s;
        }
        __syncthreads();
        if (kg < 7 && j == 0) wait_flag(&g_fp[kg * 32], soldp[kg]);
        __syncthreads();
        if (t < NN2) sP[t] = __ldcg(&g_p[t]);
        __syncthreads();
        if (t < NN2) {
            int i = t / NN, jj = t % NN;
            float a0 = sr[i] * sc[jj] + sb2[jj];
            float a1 = 0.f;
            #pragma unroll
            for (int k = 0; k < 20; k += 2) {
                a0 += sA2[i * NN + k]     * sP[k * NN + jj];
                a1 += sA2[i * NN + k + 1] * sP[(k + 1) * NN + jj];
            }
            a0 += sA2[i * NN + 20] * sP[20 * NN + jj];
            g_v[t] = a0 + a1;
        }
        __syncthreads();
        if (t == 0) { __threadfence(); publish(&g_fv[0]); }
        return;
    }

    float* red = sh;

    if (b <= 16) {
        const int jt = b - 1;
        const unsigned oldv = ld_plain(&g_fv[0]);
        const float bias = (t < 32) ? __ldg(&bf1[jt * 32 + t]) : 0.f;
        const int k0 = kg * 28;
        float w[28];
        #pragma unroll
        for (int kk = 0; kk < 28; kk++) {
            int k = k0 + kk;
            w[kk] = (k < FC1_K) ? __ldg(&Wf1[k * FC1_OUT + jt * 32 + j]) : 0.f;
        }
        wait_flag(&g_fv[0], oldv);
        float xv = (j < 28) ? __ldcg(&g_v[k0 + j]) : 0.f;
        float a0 = 0.f, a1 = 0.f, a2 = 0.f, a3 = 0.f;
        #pragma unroll
        for (int kk = 0; kk < 28; kk += 4) {
            a0 += __shfl_sync(0xffffffffu, xv, kk)     * w[kk];
            a1 += __shfl_sync(0xffffffffu, xv, kk + 1) * w[kk + 1];
            a2 += __shfl_sync(0xffffffffu, xv, kk + 2) * w[kk + 2];
            a3 += __shfl_sync(0xffffffffu, xv, kk + 3) * w[kk + 3];
        }
        red[t] = (a0 + a1) + (a2 + a3);
        __syncthreads();
        if (t < 32) {
            float s0 = red[t]       + red[t + 32];
            float s1 = red[t + 64]  + red[t + 96];
            float s2 = red[t + 128] + red[t + 160];
            float s3 = red[t + 192] + red[t + 224];
            float s4 = red[t + 256] + red[t + 288];
            float s5 = red[t + 320] + red[t + 352];
            float s6 = red[t + 384] + red[t + 416];
            float s7 = red[t + 448] + red[t + 480];
            float s  = ((s0 + s1) + (s2 + s3)) + ((s4 + s5) + (s6 + s7));
            g_x1[jt * 32 + t] = fmaxf(s + bias, 0.f);
            __syncwarp();
            if (t == 0) { __threadfence(); publish(&g_fx1[jt * 32]); }
        }
        return;
    }

    if (b <= 32) {
        const int jt = b - 17;
        unsigned oldf = 0;
        if (j == 0) oldf = ld_plain(&g_fx1[kg * 32]);
        oldf = __shfl_sync(0xffffffffu, oldf, 0);
        const float bias = (t < 32) ? __ldg(&bf2[jt * 32 + t]) : 0.f;
        const int k0 = kg * 32;
        float w[32];
        #pragma unroll
        for (int kk = 0; kk < 32; kk++)
            w[kk] = __ldg(&Wf2[(k0 + kk) * FC2_OUT + jt * 32 + j]);
        if (j == 0) wait_flag(&g_fx1[kg * 32], oldf);
        __syncwarp();
        float xv = __ldcg(&g_x1[k0 + j]);
        float a0 = 0.f, a1 = 0.f, a2 = 0.f, a3 = 0.f;
        #pragma unroll
        for (int kk = 0; kk < 32; kk += 4) {
            a0 += __shfl_sync(0xffffffffu, xv, kk)     * w[kk];
            a1 += __shfl_sync(0xffffffffu, xv, kk + 1) * w[kk + 1];
            a2 += __shfl_sync(0xffffffffu, xv, kk + 2) * w[kk + 2];
            a3 += __shfl_sync(0xffffffffu, xv, kk + 3) * w[kk + 3];
        }
        red[t] = (a0 + a1) + (a2 + a3);
        __syncthreads();
        if (t < 32) {
            float s0 = red[t]       + red[t + 32];
            float s1 = red[t + 64]  + red[t + 96];
            float s2 = red[t + 128] + red[t + 160];
            float s3 = red[t + 192] + red[t + 224];
            float s4 = red[t + 256] + red[t + 288];
            float s5 = red[t + 320] + red[t + 352];
            float s6 = red[t + 384] + red[t + 416];
            float s7 = red[t + 448] + red[t + 480];
            float s  = ((s0 + s1) + (s2 + s3)) + ((s4 + s5) + (s6 + s7));
            g_x2[jt * 32 + t] = fmaxf(s + bias, 0.f);
            __syncwarp();
            if (t == 0) { __threadfence(); publish(&g_fx2[jt * 32]); }
        }
        return;
    }

    {
        const int g3 = b - 33;
        unsigned oldf = 0;
        if (j == 0) oldf = ld_plain(&g_fx2[kg * 32]);
        oldf = __shfl_sync(0xffffffffu, oldf, 0);

        if (g3 < 7) {
            float* sXr  = sh;
            float* sW1g = sh + 384;
            float* sW2s = sh + 3072;
            float* sH   = sh + 3520;
            float* pr   = sh + 3584;
            const int R0 = g3 * 3;
            {
                const float4* X4 = (const float4*)(state + R0 * NFEAT);
                float4* d4 = (float4*)sXr;
                if (t < 96) d4[t] = X4[t];
                const float4* W14 = (const float4*)W1;
                float4* w14 = (float4*)sW1g;
                for (int i = t; i < 672; i += NTHREADS) w14[i] = W14[i];
                if (t < NN2) sW2s[t] = W2[t];
            }
            __syncthreads();
            if (t < 504) {
                int o  = t >> 3;
                int s  = t & 7;
                int ri = o / NN, jj = o % NN;
                int kk0 = s * 16;
                float a0 = 0.f, a1 = 0.f, a2 = 0.f, a3 = 0.f;
                #pragma unroll
                for (int kk = 0; kk < 16; kk += 4) {
                    a0 += sXr[ri * NFEAT + kk0 + kk]     * sW1g[(kk0 + kk)     * NN + jj];
                    a1 += sXr[ri * NFEAT + kk0 + kk + 1] * sW1g[(kk0 + kk + 1) * NN + jj];
                    a2 += sXr[ri * NFEAT + kk0 + kk + 2] * sW1g[(kk0 + kk + 2) * NN + jj];
                    a3 += sXr[ri * NFEAT + kk0 + kk + 3] * sW1g[(kk0 + kk + 3) * NN + jj];
                }
                pr[t] = (a0 + a1) + (a2 + a3);
            }
            __syncthreads();
            if (t < 63) {
                float s0 = pr[t * 8]     + pr[t * 8 + 1];
                float s1 = pr[t * 8 + 2] + pr[t * 8 + 3];
                float s2 = pr[t * 8 + 4] + pr[t * 8 + 5];
                float s3 = pr[t * 8 + 6] + pr[t * 8 + 7];
                sH[t] = (s0 + s1) + (s2 + s3);
            }
            __syncthreads();
            if (t < 63) {
                int ri = t / NN, jj = t % NN;
                float a0 = 0.f, a1 = 0.f;
                #pragma unroll
                for (int k = 0; k < 20; k += 2) {
                    a0 += sH[ri * NN + k]     * sW2s[k * NN + jj];
                    a1 += sH[ri * NN + k + 1] * sW2s[(k + 1) * NN + jj];
                }
                a0 += sH[ri * NN + 20] * sW2s[20 * NN + jj];
                g_p[(R0 + ri) * NN + jj] = a0 + a1;
            }
            __syncthreads();
            if (t == 0) { __threadfence(); publish(&g_fp[g3 * 32]); }
            __syncthreads();
        }

        const float bias = (t < 32) ? __ldg(&bf3[g3 * 32 + t]) : 0.f;
        const int k0 = kg * 32;
        float w[32];
        #pragma unroll
        for (int kk = 0; kk < 32; kk++)
            w[kk] = __ldg(&Wf3[(k0 + kk) * FC3_OUT + g3 * 32 + j]);
        if (j == 0) wait_flag(&g_fx2[kg * 32], oldf);
        __syncwarp();
        float xv = __ldcg(&g_x2[k0 + j]);
        float a0 = 0.f, a1 = 0.f, a2 = 0.f, a3 = 0.f;
        #pragma unroll
        for (int kk = 0; kk < 32; kk += 4) {
            a0 += __shfl_sync(0xffffffffu, xv, kk)     * w[kk];
            a1 += __shfl_sync(0xffffffffu, xv, kk + 1) * w[kk + 1];
            a2 += __shfl_sync(0xffffffffu, xv, kk + 2) * w[kk + 2];
            a3 += __shfl_sync(0xffffffffu, xv, kk + 3) * w[kk + 3];
        }
        red[t] = (a0 + a1) + (a2 + a3);
        __syncthreads();
        if (t < 32) {
            float s0 = red[t]       + red[t + 32];
            float s1 = red[t + 64]  + red[t + 96];
            float s2 = red[t + 128] + red[t + 160];
            float s3 = red[t + 192] + red[t + 224];
            float s4 = red[t + 256] + red[t + 288];
            float s5 = red[t + 320] + red[t + 352];
            float s6 = red[t + 384] + red[t + 416];
            float s7 = red[t + 448] + red[t + 480];
            float s  = ((s0 + s1) + (s2 + s3)) + ((s4 + s5) + (s6 + s7));
            out[g3 * 32 + t] = fmaxf(s + bias, 0.f);
        }
    }
}

// ---------------------------------------------------------------------------
extern "C" void kernel_launch(void* const* d_in, const int* in_sizes, int n_in,
                              void* d_out, int out_size)
{
    const float* state = (const float*)d_in[0];
    const int*   edges = (const int*)  d_in[1];
    const int n_edges  = in_sizes[1] / 2;

    const float* W1  = (const float*)d_in[2];
    const float* b1  = (const float*)d_in[3];
    const float* W2  = (const float*)d_in[4];
    const float* b2  = (const float*)d_in[5];
    const float* Wf1 = (const float*)d_in[6];
    const float* bf1 = (const float*)d_in[7];
    const float* Wf2 = (const float*)d_in[8];
    const float* bf2 = (const float*)d_in[9];
    const float* Wf3 = (const float*)d_in[10];
    const float* bf3 = (const float*)d_in[11];
    float* out = (float*)d_out;

    static int use16 = -1;
    if (use16 < 0) {
        cudaFuncSetAttribute(cluster_net_kernel,
                             cudaFuncAttributeNonPortableClusterSizeAllowed, 1);
        cudaLaunchConfig_t probe = {};
        probe.gridDim  = {CLN, 1, 1};
        probe.blockDim = {CNT, 1, 1};
        cudaLaunchAttribute pa[1];
        pa[0].id = cudaLaunchAttributeClusterDimension;
        pa[0].val.clusterDim = {CLN, 1, 1};
        probe.attrs = pa;
        probe.numAttrs = 1;
        int nclust = 0;
        cudaError_t e = cudaOccupancyMaxActiveClusters(&nclust, cluster_net_kernel, &probe);
        use16 = (e == cudaSuccess && nclust >= 1) ? 1 : 0;
        cudaGetLastError();
    }

    if (use16) {
        cudaLaunchConfig_t cfg = {};
        cfg.gridDim  = {CLN, 1, 1};
        cfg.blockDim = {CNT, 1, 1};
        cudaLaunchAttribute attrs[1];
        attrs[0].id = cudaLaunchAttributeClusterDimension;
        attrs[0].val.clusterDim = {CLN, 1, 1};
        cfg.attrs = attrs;
        cfg.numAttrs = 1;
        cudaLaunchKernelEx(&cfg, cluster_net_kernel,
                           state, edges, n_edges, W1, b1, W2, b2,
                           Wf1, bf1, Wf2, bf2, Wf3, bf3, out);
    } else {
        fused_net_kernel<<<NBLK, NTHREADS>>>(
            state, edges, n_edges, W1, b1, W2, b2,
            Wf1, bf1, Wf2, bf2, Wf3, bf3, out);
    }
}